// round 13
// baseline (speedup 1.0000x reference)
#include <cuda_runtime.h>
#include <cuda_bf16.h>

// Scratch (allocation-free rule: __device__ globals).
#define MAX_S 262144
#define MAX_N 2097152
__device__ int      g_head[2 * MAX_S];  // two chains per segment (row parity)
__device__ unsigned g_last[MAX_S];      // bit pattern of segment-max timestamp (all t > 0)
__device__ int      g_next[MAX_N];      // per-row list link (-1 = end)

#define BETA 0.8f

// ---------------------------------------------------------------------------
// Single pre-pass: build TWO per-segment linked lists (split by row parity so
// each warp can chase two chains concurrently) AND the segment-max of
// timestamps (uint order == float order since all t > 0; heads init to -1,
// last init to 0 => empty segments output last_t = 0, matching the
// reference's where(tw>0, last_t, 0)).  next[] writes are coalesced.
__global__ void twma_link_kernel(const int*   __restrict__ ids,
                                 const float* __restrict__ ts,
                                 int N) {
    int i = blockIdx.x * blockDim.x + threadIdx.x;
    if (i < N) {
        int s = ids[i];
        atomicMax(&g_last[s], __float_as_uint(ts[i]));
        g_next[i] = atomicExch(&g_head[2 * s + (i & 1)], i);
    }
}

// ---------------------------------------------------------------------------
// One warp per SEGMENT, full row (NC compile-time float4 chunks per lane,
// NC=2 for D=256).  Walks BOTH parity chains concurrently: 2 chase loads in
// flight + 2*NC independent 16B gathers per lane per iteration, halving the
// serial L2-latency depth vs a single chain.
template <int NC>
__global__ void twma_seg_row_kernel(const float4* __restrict__ msg,
                                    const float*  __restrict__ ts,
                                    float* __restrict__ out,
                                    int S, int C /* = NC*32 */, int D) {
    int seg  = (blockIdx.x * blockDim.x + threadIdx.x) >> 5;
    if (seg >= S) return;
    int lane = threadIdx.x & 31;

    unsigned lb = g_last[seg];
    float    lt = __uint_as_float(lb);

    float4 acc[NC];
    #pragma unroll
    for (int j = 0; j < NC; j++) acc[j] = make_float4(0.f, 0.f, 0.f, 0.f);
    float tw = 0.f;

    int i0 = g_head[2 * seg];
    int i1 = g_head[2 * seg + 1];

    // Dual-chain main loop.
    while (i0 >= 0 && i1 >= 0) {
        int n0 = g_next[i0];                  // both chases issue up front
        int n1 = g_next[i1];
        const float4* r0 = msg + (long long)i0 * C + lane;
        const float4* r1 = msg + (long long)i1 * C + lane;
        float w0 = __expf(BETA * (ts[i0] - lt));
        float w1 = __expf(BETA * (ts[i1] - lt));
        tw += w0 + w1;
        #pragma unroll
        for (int j = 0; j < NC; j++) {
            float4 m0 = r0[j * 32];
            float4 m1 = r1[j * 32];
            acc[j].x += w0 * m0.x + w1 * m1.x;
            acc[j].y += w0 * m0.y + w1 * m1.y;
            acc[j].z += w0 * m0.z + w1 * m1.z;
            acc[j].w += w0 * m0.w + w1 * m1.w;
        }
        i0 = n0; i1 = n1;
    }
    // Drain whichever chain remains.
    int i = (i0 >= 0) ? i0 : i1;
    while (i >= 0) {
        int nx = g_next[i];
        const float4* row = msg + (long long)i * C + lane;
        float w = __expf(BETA * (ts[i] - lt));
        tw += w;
        #pragma unroll
        for (int j = 0; j < NC; j++) {
            float4 m = row[j * 32];
            acc[j].x += w * m.x;
            acc[j].y += w * m.y;
            acc[j].z += w * m.z;
            acc[j].w += w * m.w;
        }
        i = nx;
    }

    float inv = (tw > 0.f) ? (1.0f / tw) : 0.0f;
    float4* dst = reinterpret_cast<float4*>(out) + (long long)seg * C + lane;
    #pragma unroll
    for (int j = 0; j < NC; j++) {
        dst[j * 32] = make_float4(acc[j].x * inv, acc[j].y * inv,
                                  acc[j].z * inv, acc[j].w * inv);
    }

    if (lane == 0) {
        out[(long long)S * D + seg] = __uint_as_float(lb);  // 0 for empty segs
    }
}

// ---------------------------------------------------------------------------
// Generic fallback: one warp per (segment, 128-float column tile), dual-chain
// walk per tile.
__global__ void twma_seg_kernel(const float4* __restrict__ msg,
                                const float*  __restrict__ ts,
                                float* __restrict__ out,
                                int S, int C, int D) {
    int gw   = (blockIdx.x * blockDim.x + threadIdx.x) >> 5;
    int lane = threadIdx.x & 31;
    int tilesPerSeg = C >> 5;
    int seg  = gw / tilesPerSeg;
    int tile = gw - seg * tilesPerSeg;
    if (seg >= S) return;

    unsigned lb  = g_last[seg];
    float    lt  = __uint_as_float(lb);
    int      col = (tile << 5) + lane;

    float4 acc = make_float4(0.f, 0.f, 0.f, 0.f);
    float  tw  = 0.f;

    for (int half = 0; half < 2; half++) {
        int i = g_head[2 * seg + half];
        while (i >= 0) {
            int   nx = g_next[i];
            float w  = __expf(BETA * (ts[i] - lt));
            tw += w;
            float4 m = msg[(long long)i * C + col];
            acc.x += w * m.x;
            acc.y += w * m.y;
            acc.z += w * m.z;
            acc.w += w * m.w;
            i = nx;
        }
    }

    float inv = (tw > 0.f) ? (1.0f / tw) : 0.0f;
    reinterpret_cast<float4*>(out)[(long long)seg * C + col] =
        make_float4(acc.x * inv, acc.y * inv, acc.z * inv, acc.w * inv);

    if (tile == 0 && lane == 0) {
        out[(long long)S * D + seg] = __uint_as_float(lb);
    }
}

// ---------------------------------------------------------------------------
extern "C" void kernel_launch(void* const* d_in, const int* in_sizes, int n_in,
                              void* d_out, int out_size) {
    const float* msg = (const float*)d_in[0];   // [N, D] fp32
    const float* ts  = (const float*)d_in[1];   // [N]    fp32
    const int*   ids = (const int*)d_in[2];     // [N]    int32

    int N = in_sizes[1];
    int D = in_sizes[0] / N;          // 256
    int S = out_size / (D + 1);       // 65536 (out = S*D agg + S last_t)
    int C = D / 4;

    float* out = (float*)d_out;

    // Init scratch: heads = -1 (0xFF bytes), last = 0.  Memset nodes only.
    void* p_head = nullptr;
    void* p_last = nullptr;
    cudaGetSymbolAddress(&p_head, g_head);
    cudaGetSymbolAddress(&p_last, g_last);
    cudaMemsetAsync(p_head, 0xFF, (size_t)(2 * S) * sizeof(int));
    cudaMemsetAsync(p_last, 0,    (size_t)S * sizeof(unsigned));

    twma_link_kernel<<<(N + 255) / 256, 256>>>(ids, ts, N);

    if (C == 64) {
        long long threads = (long long)S * 32;
        unsigned blocks = (unsigned)((threads + 255) / 256);
        twma_seg_row_kernel<2><<<blocks, 256>>>((const float4*)msg, ts, out,
                                                S, C, D);
    } else if (C == 32) {
        long long threads = (long long)S * 32;
        unsigned blocks = (unsigned)((threads + 255) / 256);
        twma_seg_row_kernel<1><<<blocks, 256>>>((const float4*)msg, ts, out,
                                                S, C, D);
    } else {
        long long warps   = (long long)S * (C >> 5);
        long long threads = warps * 32;
        unsigned blocks   = (unsigned)((threads + 255) / 256);
        twma_seg_kernel<<<blocks, 256>>>((const float4*)msg, ts, out, S, C, D);
    }
}

// round 14
// speedup vs baseline: 1.1139x; 1.1139x over previous
#include <cuda_runtime.h>
#include <cuda_bf16.h>
#include <math.h>

// Scratch (allocation-free rule: __device__ globals).
#define MAX_S 262144
#define MAX_N 2097152
__device__ int g_head[MAX_S];    // per-segment list head (-1 = empty)
__device__ int g_next[MAX_N];    // per-row list link (-1 = end)

#define BETA 0.8f

// ---------------------------------------------------------------------------
// Single pre-pass: build per-segment linked lists.  ONE random L2 atomic per
// row (the segment-max is now computed online in the gather, which visits
// every row anyway).  next[] writes are coalesced.
__global__ void twma_link_kernel(const int* __restrict__ ids, int N) {
    int i = blockIdx.x * blockDim.x + threadIdx.x;
    if (i < N) {
        g_next[i] = atomicExch(&g_head[ids[i]], i);
    }
}

// ---------------------------------------------------------------------------
// One warp per SEGMENT, full row (NC compile-time float4 chunks per lane,
// NC=2 for D=256).  Single list walk (R10 form — measured best: 182us @ 82%
// DRAM).  Segment max of ts computed ONLINE: running max mt; on a new max
// (warp-uniform, rare) rescale acc/tw by exp(beta*(mt_old - mt_new)).
// mt starts at -inf: first iteration's rescale factor exp(-inf)=0 zeroes the
// already-zero accumulators, so no special case is needed.
template <int NC>
__global__ void twma_seg_row_kernel(const float4* __restrict__ msg,
                                    const float*  __restrict__ ts,
                                    float* __restrict__ out,
                                    int S, int C /* = NC*32 */, int D) {
    int seg  = (blockIdx.x * blockDim.x + threadIdx.x) >> 5;
    if (seg >= S) return;
    int lane = threadIdx.x & 31;

    float4 acc[NC];
    #pragma unroll
    for (int j = 0; j < NC; j++) acc[j] = make_float4(0.f, 0.f, 0.f, 0.f);
    float tw = 0.f;
    float mt = -INFINITY;

    int i = g_head[seg];
    while (i >= 0) {
        int nx = g_next[i];                   // issue the serial chase first
        const float4* row = msg + (long long)i * C + lane;
        float t = ts[i];                      // broadcast
        if (t > mt) {                         // warp-uniform, ~3x per chain
            float sc = __expf(BETA * (mt - t));   // 0 on first iteration
            mt = t;
            tw *= sc;
            #pragma unroll
            for (int j = 0; j < NC; j++) {
                acc[j].x *= sc; acc[j].y *= sc;
                acc[j].z *= sc; acc[j].w *= sc;
            }
        }
        float w = __expf(BETA * (t - mt));    // w in (0,1]
        tw += w;
        #pragma unroll
        for (int j = 0; j < NC; j++) {
            float4 m = row[j * 32];           // NC independent gathers
            acc[j].x += w * m.x;
            acc[j].y += w * m.y;
            acc[j].z += w * m.z;
            acc[j].w += w * m.w;
        }
        i = nx;
    }

    float inv = (tw > 0.f) ? (1.0f / tw) : 0.0f;
    float4* dst = reinterpret_cast<float4*>(out) + (long long)seg * C + lane;
    #pragma unroll
    for (int j = 0; j < NC; j++) {
        dst[j * 32] = make_float4(acc[j].x * inv, acc[j].y * inv,
                                  acc[j].z * inv, acc[j].w * inv);
    }

    if (lane == 0) {
        out[(long long)S * D + seg] = (tw > 0.f) ? mt : 0.0f;  // empty -> 0
    }
}

// ---------------------------------------------------------------------------
// Generic fallback: one warp per (segment, 128-float column tile), same
// online-max walk per tile.
__global__ void twma_seg_kernel(const float4* __restrict__ msg,
                                const float*  __restrict__ ts,
                                float* __restrict__ out,
                                int S, int C, int D) {
    int gw   = (blockIdx.x * blockDim.x + threadIdx.x) >> 5;
    int lane = threadIdx.x & 31;
    int tilesPerSeg = C >> 5;
    int seg  = gw / tilesPerSeg;
    int tile = gw - seg * tilesPerSeg;
    if (seg >= S) return;

    int col = (tile << 5) + lane;

    float4 acc = make_float4(0.f, 0.f, 0.f, 0.f);
    float  tw  = 0.f;
    float  mt  = -INFINITY;

    int i = g_head[seg];
    while (i >= 0) {
        int   nx = g_next[i];
        float t  = ts[i];
        if (t > mt) {
            float sc = __expf(BETA * (mt - t));
            mt = t;
            tw *= sc;
            acc.x *= sc; acc.y *= sc; acc.z *= sc; acc.w *= sc;
        }
        float w = __expf(BETA * (t - mt));
        tw += w;
        float4 m = msg[(long long)i * C + col];
        acc.x += w * m.x;
        acc.y += w * m.y;
        acc.z += w * m.z;
        acc.w += w * m.w;
        i = nx;
    }

    float inv = (tw > 0.f) ? (1.0f / tw) : 0.0f;
    reinterpret_cast<float4*>(out)[(long long)seg * C + col] =
        make_float4(acc.x * inv, acc.y * inv, acc.z * inv, acc.w * inv);

    if (tile == 0 && lane == 0) {
        out[(long long)S * D + seg] = (tw > 0.f) ? mt : 0.0f;
    }
}

// ---------------------------------------------------------------------------
extern "C" void kernel_launch(void* const* d_in, const int* in_sizes, int n_in,
                              void* d_out, int out_size) {
    const float* msg = (const float*)d_in[0];   // [N, D] fp32
    const float* ts  = (const float*)d_in[1];   // [N]    fp32
    const int*   ids = (const int*)d_in[2];     // [N]    int32

    int N = in_sizes[1];
    int D = in_sizes[0] / N;          // 256
    int S = out_size / (D + 1);       // 65536 (out = S*D agg + S last_t)
    int C = D / 4;

    float* out = (float*)d_out;

    // Init scratch: heads = -1 (0xFF bytes).  Single memset node.
    void* p_head = nullptr;
    cudaGetSymbolAddress(&p_head, g_head);
    cudaMemsetAsync(p_head, 0xFF, (size_t)S * sizeof(int));

    twma_link_kernel<<<(N + 255) / 256, 256>>>(ids, N);

    if (C == 64) {
        // D=256: one warp per segment, 2 float4 chunks per lane.
        long long threads = (long long)S * 32;
        unsigned blocks = (unsigned)((threads + 255) / 256);
        twma_seg_row_kernel<2><<<blocks, 256>>>((const float4*)msg, ts, out,
                                                S, C, D);
    } else if (C == 32) {
        long long threads = (long long)S * 32;
        unsigned blocks = (unsigned)((threads + 255) / 256);
        twma_seg_row_kernel<1><<<blocks, 256>>>((const float4*)msg, ts, out,
                                                S, C, D);
    } else {
        long long warps   = (long long)S * (C >> 5);
        long long threads = warps * 32;
        unsigned blocks   = (unsigned)((threads + 255) / 256);
        twma_seg_kernel<<<blocks, 256>>>((const float4*)msg, ts, out, S, C, D);
    }
}

// round 15
// speedup vs baseline: 1.1344x; 1.0184x over previous
#include <cuda_runtime.h>
#include <cuda_bf16.h>
#include <math.h>

// Scratch (allocation-free rule: __device__ globals).
// Zero-init at module load is the invariant: heads use 0 = empty (row stored
// as i+1), and the seg kernel restores head=0 after consuming each segment,
// so NO per-launch init pass is needed.
#define MAX_S 262144
#define MAX_N 2097152
__device__ int  g_head[MAX_S];    // i+1 of head row; 0 = empty
__device__ int2 g_link[MAX_N];    // {next (i+1 enc, 0=end), ts bits} per row

#define BETA 0.8f

// ---------------------------------------------------------------------------
// Single pre-pass: build per-segment linked lists.  One random L2 atomic per
// row; the chase payload carries BOTH the next pointer and the row's
// timestamp bits, so the gather loop needs a single LDG.64 per hop.
// g_link writes are coalesced.
__global__ void twma_link_kernel(const int*   __restrict__ ids,
                                 const float* __restrict__ ts,
                                 int N) {
    int i = blockIdx.x * blockDim.x + threadIdx.x;
    if (i < N) {
        int prev = atomicExch(&g_head[ids[i]], i + 1);
        g_link[i] = make_int2(prev, __float_as_int(ts[i]));
    }
}

// ---------------------------------------------------------------------------
// One warp per SEGMENT, full row (NC compile-time float4 chunks per lane,
// NC=2 for D=256).  Single list walk (measured-best form: 182us @ 82% DRAM).
// Segment max of ts computed ONLINE: running max mt; on a new max
// (warp-uniform, rare) rescale acc/tw by exp(beta*(mt_old - mt_new)).
// mt starts at -inf: first iteration's rescale factor exp(-inf)=0 zeroes the
// already-zero accumulators, so no special case is needed.
// After reading its head, the warp resets it to 0 (replay invariant).
template <int NC>
__global__ void twma_seg_row_kernel(const float4* __restrict__ msg,
                                    float* __restrict__ out,
                                    int S, int C /* = NC*32 */, int D) {
    int seg  = (blockIdx.x * blockDim.x + threadIdx.x) >> 5;
    if (seg >= S) return;
    int lane = threadIdx.x & 31;

    int p = g_head[seg];                      // i+1 encoding, 0 = empty
    if (lane == 0 && p != 0) g_head[seg] = 0; // restore zero invariant

    float4 acc[NC];
    #pragma unroll
    for (int j = 0; j < NC; j++) acc[j] = make_float4(0.f, 0.f, 0.f, 0.f);
    float tw = 0.f;
    float mt = -INFINITY;

    while (p > 0) {
        int  row = p - 1;
        int2 ln  = g_link[row];               // chase + ts in ONE LDG.64
        const float4* rp = msg + (long long)row * C + lane;
        float t = __int_as_float(ln.y);
        if (t > mt) {                         // warp-uniform, ~3x per chain
            float sc = __expf(BETA * (mt - t));   // 0 on first iteration
            mt = t;
            tw *= sc;
            #pragma unroll
            for (int j = 0; j < NC; j++) {
                acc[j].x *= sc; acc[j].y *= sc;
                acc[j].z *= sc; acc[j].w *= sc;
            }
        }
        float w = __expf(BETA * (t - mt));    // w in (0,1]
        tw += w;
        #pragma unroll
        for (int j = 0; j < NC; j++) {
            float4 m = rp[j * 32];            // NC independent gathers
            acc[j].x += w * m.x;
            acc[j].y += w * m.y;
            acc[j].z += w * m.z;
            acc[j].w += w * m.w;
        }
        p = ln.x;
    }

    float inv = (tw > 0.f) ? (1.0f / tw) : 0.0f;
    float4* dst = reinterpret_cast<float4*>(out) + (long long)seg * C + lane;
    #pragma unroll
    for (int j = 0; j < NC; j++) {
        dst[j * 32] = make_float4(acc[j].x * inv, acc[j].y * inv,
                                  acc[j].z * inv, acc[j].w * inv);
    }

    if (lane == 0) {
        out[(long long)S * D + seg] = (tw > 0.f) ? mt : 0.0f;  // empty -> 0
    }
}

// ---------------------------------------------------------------------------
// Generic fallback: one warp per (segment, 128-float column tile), same
// online-max walk per tile.  Only the LAST tile-warp (tile 0 handles output
// tail) — head reset done by tile 0 only after all tiles read it is racy, so
// the fallback instead resets head in a dedicated pass-free way: every tile
// reads head first, and tile 0 resets it (reads of other tiles may race with
// the reset ONLY within the same kernel, where all reads happen before any
// long-running walk completes; to stay safe the fallback does NOT reset and
// instead relies on link overwriting non-empty heads -- acceptable because
// the fallback path is unused for this problem's D=256/D=128 shapes).
__global__ void twma_seg_kernel(const float4* __restrict__ msg,
                                float* __restrict__ out,
                                int S, int C, int D) {
    int gw   = (blockIdx.x * blockDim.x + threadIdx.x) >> 5;
    int lane = threadIdx.x & 31;
    int tilesPerSeg = C >> 5;
    int seg  = gw / tilesPerSeg;
    int tile = gw - seg * tilesPerSeg;
    if (seg >= S) return;

    int col = (tile << 5) + lane;

    float4 acc = make_float4(0.f, 0.f, 0.f, 0.f);
    float  tw  = 0.f;
    float  mt  = -INFINITY;

    int p = g_head[seg];
    while (p > 0) {
        int  row = p - 1;
        int2 ln  = g_link[row];
        float t  = __int_as_float(ln.y);
        if (t > mt) {
            float sc = __expf(BETA * (mt - t));
            mt = t;
            tw *= sc;
            acc.x *= sc; acc.y *= sc; acc.z *= sc; acc.w *= sc;
        }
        float w = __expf(BETA * (t - mt));
        tw += w;
        float4 m = msg[(long long)row * C + col];
        acc.x += w * m.x;
        acc.y += w * m.y;
        acc.z += w * m.z;
        acc.w += w * m.w;
        p = ln.x;
    }

    float inv = (tw > 0.f) ? (1.0f / tw) : 0.0f;
    reinterpret_cast<float4*>(out)[(long long)seg * C + col] =
        make_float4(acc.x * inv, acc.y * inv, acc.z * inv, acc.w * inv);

    if (tile == 0 && lane == 0) {
        out[(long long)S * D + seg] = (tw > 0.f) ? mt : 0.0f;
    }
}

// Reset pass used only with the generic fallback (multi-tile walkers can't
// safely reset heads in-kernel).
__global__ void twma_reset_kernel(int S) {
    int i = blockIdx.x * blockDim.x + threadIdx.x;
    if (i < S) g_head[i] = 0;
}

// ---------------------------------------------------------------------------
extern "C" void kernel_launch(void* const* d_in, const int* in_sizes, int n_in,
                              void* d_out, int out_size) {
    const float* msg = (const float*)d_in[0];   // [N, D] fp32
    const float* ts  = (const float*)d_in[1];   // [N]    fp32
    const int*   ids = (const int*)d_in[2];     // [N]    int32

    int N = in_sizes[1];
    int D = in_sizes[0] / N;          // 256
    int S = out_size / (D + 1);       // 65536 (out = S*D agg + S last_t)
    int C = D / 4;

    float* out = (float*)d_out;

    twma_link_kernel<<<(N + 255) / 256, 256>>>(ids, ts, N);

    if (C == 64) {
        // D=256: one warp per segment, 2 float4 chunks per lane.
        long long threads = (long long)S * 32;
        unsigned blocks = (unsigned)((threads + 255) / 256);
        twma_seg_row_kernel<2><<<blocks, 256>>>((const float4*)msg, out,
                                                S, C, D);
    } else if (C == 32) {
        long long threads = (long long)S * 32;
        unsigned blocks = (unsigned)((threads + 255) / 256);
        twma_seg_row_kernel<1><<<blocks, 256>>>((const float4*)msg, out,
                                                S, C, D);
    } else {
        long long warps   = (long long)S * (C >> 5);
        long long threads = warps * 32;
        unsigned blocks   = (unsigned)((threads + 255) / 256);
        twma_seg_kernel<<<blocks, 256>>>((const float4*)msg, out, S, C, D);
        twma_reset_kernel<<<(S + 255) / 256, 256>>>(S);
    }
}